// round 15
// baseline (speedup 1.0000x reference)
#include <cuda_runtime.h>
#include <cuda_fp16.h>
#include <math.h>
#include <stdint.h>

// ---------------------------------------------------------------- constants
#define BB   16
#define NC   1024
#define NF   4096
#define CC   256
#define MM   (BB * NF)      // 65536 fine points
#define MC   (BB * NC)      // 16384 coarse points

// ---------------------------------------------------------------- scratch
__device__ __align__(16) __half g_Xh[MC * 256];        // x  (fp16)
__device__ __align__(16) __half g_Sh[MM * 256];        // x_skip (fp16)
__device__ __align__(16) __half g_H1h[MM * 512];       // layer1 out (fp16)
__device__ __align__(16) __half g_Z[MC * 512];         // x @ W1a (fp16)
__device__ __align__(16) __half g_W1aT[512 * 256];     // [N=512][K=256]
__device__ __align__(16) __half g_W1bT[512 * 256];
__device__ __align__(16) __half g_W2T[256 * 512];      // [N=256][K=512]
__device__ int   g_idx[MM * 3];
__device__ float g_w[MM * 3];

// ---------------------------------------------------------------- helpers
__device__ __forceinline__ uint32_t smem_u32(const void* p) {
    uint32_t a;
    asm("{ .reg .u64 t; cvta.to.shared.u64 t, %1; cvt.u32.u64 %0, t; }"
        : "=r"(a) : "l"(p));
    return a;
}
__device__ __forceinline__ void cp16(uint32_t dst, const void* src) {
    asm volatile("cp.async.cg.shared.global [%0], [%1], 16;" :: "r"(dst), "l"(src));
}
__device__ __forceinline__ void ldsm4(uint32_t* r, uint32_t addr) {
    asm volatile("ldmatrix.sync.aligned.m8n8.x4.shared.b16 {%0,%1,%2,%3}, [%4];"
        : "=r"(r[0]), "=r"(r[1]), "=r"(r[2]), "=r"(r[3]) : "r"(addr));
}
__device__ __forceinline__ void mma16816(float* d, const uint32_t* a, const uint32_t* b) {
    asm volatile("mma.sync.aligned.m16n8k16.row.col.f32.f16.f16.f32 "
        "{%0,%1,%2,%3}, {%4,%5,%6,%7}, {%8,%9}, {%0,%1,%2,%3};"
        : "+f"(d[0]), "+f"(d[1]), "+f"(d[2]), "+f"(d[3])
        : "r"(a[0]), "r"(a[1]), "r"(a[2]), "r"(a[3]), "r"(b[0]), "r"(b[1]));
}

// ---------------------------------------------------------------- merged prep
#define PB_KNN   0
#define PB_X     256
#define PB_S     (PB_X + 4096)
#define PB_T1    (PB_S + 16384)
#define PB_T2    (PB_T1 + 128)
#define PB_T3    (PB_T2 + 128)
#define PB_TAIL  (PB_T3 + 128)       // 21120
#define PB_END   (PB_TAIL + 768)     // 21888

__global__ __launch_bounds__(256)
void prep_kernel(const float* __restrict__ pos_c, const float* __restrict__ pos_f,
                 const float* __restrict__ x, const float* __restrict__ x_skip,
                 const float* __restrict__ W1, const float* __restrict__ W2,
                 const int* __restrict__ batch_skip,
                 float* __restrict__ out) {
    __shared__ float4 sh4[NC];            // 16 KB; aliased by transpose
    const int bid = blockIdx.x, tid = threadIdx.x;

    if (bid < PB_X) {
        // ---------------- KNN ----------------
        int i = bid * 256 + tid;
        int b = i >> 12;
        const float* pc = pos_c + (size_t)b * NC * 3;
        for (int t = tid; t < NC; t += 256)
            sh4[t] = make_float4(pc[t * 3 + 0], pc[t * 3 + 1], pc[t * 3 + 2], 0.0f);
        __syncthreads();

        float px = pos_f[i * 3 + 0], py = pos_f[i * 3 + 1], pz = pos_f[i * 3 + 2];
        float d0 = INFINITY, d1 = INFINITY, d2 = INFINITY;
        int   i0 = 0, i1 = 0, i2 = 0;
        #pragma unroll 4
        for (int j = 0; j < NC; j++) {
            float4 p = sh4[j];
            float dx = px - p.x, dy = py - p.y, dz = pz - p.z;
            float d = dx * dx + dy * dy + dz * dz;
            if (d < d2) {
                if (d < d1) {
                    if (d < d0) { d2 = d1; i2 = i1; d1 = d0; i1 = i0; d0 = d; i0 = j; }
                    else        { d2 = d1; i2 = i1; d1 = d;  i1 = j; }
                } else          { d2 = d;  i2 = j; }
            }
        }
        float w0 = 1.0f / (d0 + 1e-16f), w1 = 1.0f / (d1 + 1e-16f), w2 = 1.0f / (d2 + 1e-16f);
        float inv = 1.0f / (w0 + w1 + w2);
        int base = b * NC;
        g_idx[i * 3 + 0] = base + i0;  g_idx[i * 3 + 1] = base + i1;  g_idx[i * 3 + 2] = base + i2;
        g_w[i * 3 + 0] = w0 * inv;     g_w[i * 3 + 1] = w1 * inv;     g_w[i * 3 + 2] = w2 * inv;
    } else if (bid < PB_T1) {
        // ---------------- fp32 -> fp16 converts ----------------
        const float* src;  __half* dst;  int t;
        if (bid < PB_S) { t = (bid - PB_X) * 256 + tid;  src = x;      dst = g_Xh; }
        else            { t = (bid - PB_S) * 256 + tid;  src = x_skip; dst = g_Sh; }
        float4 v = ((const float4*)src)[t];
        __half h[4];
        h[0] = __float2half_rn(v.x);  h[1] = __float2half_rn(v.y);
        h[2] = __float2half_rn(v.z);  h[3] = __float2half_rn(v.w);
        ((uint2*)dst)[t] = *(uint2*)h;
    } else if (bid < PB_TAIL) {
        // ---------------- weight transposes ----------------
        float* tt = (float*)sh4;              // 32x33 tile
        const float* in;  __half* oh;  int N, Kt, b2;
        if (bid < PB_T2)      { b2 = bid - PB_T1; in = W1;             oh = g_W1aT; N = 512; Kt = 256; }
        else if (bid < PB_T3) { b2 = bid - PB_T2; in = W1 + 256 * 512; oh = g_W1bT; N = 512; Kt = 256; }
        else                  { b2 = bid - PB_T3; in = W2;             oh = g_W2T;  N = 256; Kt = 512; }
        int nbx = N / 32;
        int n0 = (b2 % nbx) * 32, k0 = (b2 / nbx) * 32;
        int xx = tid & 31, yy = tid >> 5;
        for (int j = yy; j < 32; j += 8)
            tt[j * 33 + xx] = in[(size_t)(k0 + j) * N + n0 + xx];
        __syncthreads();
        for (int j = yy; j < 32; j += 8)
            oh[(size_t)(n0 + j) * Kt + k0 + xx] = __float2half_rn(tt[xx * 33 + j]);
    } else {
        // ---------------- tail outputs ----------------
        int t = (bid - PB_TAIL) * 256 + tid;
        const size_t POS_OFF = (size_t)MM * CC;
        const size_t BAT_OFF = POS_OFF + (size_t)MM * 3;
        out[POS_OFF + t] = ((const float*)pos_f)[t];   // pos_f == pos_skip
        if (t < MM) out[BAT_OFF + t] = (float)batch_skip[t];
    }
}

// ---------------------------------------------------------------- mma.sync GEMM
// CTA 128x64, warp tile 32x32 (8 warps: 4M x 2N), BK=32, 4-stage cp.async,
// rolling wait_group 1 (r10-proven invariant: stages kt, kt+1 complete at
// loop top), fragment double-buffering. 3 CTAs/SM = 24 warps (6/SMSP).
// MODE 0: C -> fp16 (Z)   MODE 1: relu(C+b+gather(Z)) -> fp16 (H1)
// MODE 2: relu(C+b) -> fp32 (out)
#define A_TILE_B  10240               // 128 rows * 80B
#define B_TILE_B  5120                // 64 rows * 80B
#define STG_B     (A_TILE_B + B_TILE_B)   // 15360
#define NSTG      4
#define GEMM_SMEM (NSTG * STG_B)          // 61440

template<int MODE>
__global__ __launch_bounds__(256, 3)
void gemm_mma(const __half* __restrict__ A, const __half* __restrict__ B,
              const float* __restrict__ bias, const __half* __restrict__ Zt,
              float* __restrict__ outF, __half* __restrict__ outH,
              int K, int ldout) {
    extern __shared__ __align__(128) char smem[];
    const uint32_t sbase = smem_u32(smem);
    const int tid  = threadIdx.x;
    const int wid  = tid >> 5, lane = tid & 31;
    const int wm   = (wid >> 1) * 32;          // 0..96 (4 M-warps)
    const int wn   = (wid & 1) * 32;           // 0/32  (2 N-warps)
    const int bm   = blockIdx.y * 128, bn = blockIdx.x * 64;
    const int KT   = K >> 5;
    const int rA = tid >> 2, qA = tid & 3;     // 16B chunk decomposition

    auto load_tile = [&](int kt, int stg) {
        const uint32_t sb = sbase + stg * STG_B;
        const size_t ka = (size_t)kt * 32;
        #pragma unroll
        for (int l = 0; l < 2; l++) {          // A: 128 rows x 4 chunks
            int r = rA + l * 64;
            cp16(sb + r * 80 + qA * 16, A + (size_t)(bm + r) * K + ka + qA * 8);
        }
        {                                       // B: 64 rows x 4 chunks
            int r = rA;                         // 0..63
            if (r < 64)
                cp16(sb + A_TILE_B + r * 80 + qA * 16,
                     B + (size_t)(bn + r) * K + ka + qA * 8);
        }
        asm volatile("cp.async.commit_group;" ::: "memory");
    };

    float acc[2][4][4];
    #pragma unroll
    for (int a = 0; a < 2; a++)
        #pragma unroll
        for (int b = 0; b < 4; b++)
            #pragma unroll
            for (int c = 0; c < 4; c++) acc[a][b][c] = 0.0f;

    const int lmr = (lane & 7) + ((lane >> 3) & 1) * 8;
    const int lmc = (lane >> 4) & 1;
    const uint32_t aBase = (wm + lmr) * 80 + lmc * 16;
    const uint32_t bBase = A_TILE_B + (wn + lmr) * 80 + lmc * 16;

    uint32_t curA[2][4], curB[4][2], nxtA[2][4], nxtB[4][2];

    auto ldsA = [&](uint32_t (*fr)[4], uint32_t sb, int kc) {
        #pragma unroll
        for (int mt = 0; mt < 2; mt++)
            ldsm4(fr[mt], sb + aBase + mt * 16 * 80 + kc * 32);
    };
    auto ldsB = [&](uint32_t (*fr)[2], uint32_t sb, int kc) {
        #pragma unroll
        for (int bt = 0; bt < 2; bt++) {
            uint32_t t4[4];
            ldsm4(t4, sb + bBase + bt * 16 * 80 + kc * 32);
            fr[bt * 2][0] = t4[0];     fr[bt * 2][1] = t4[2];
            fr[bt * 2 + 1][0] = t4[1]; fr[bt * 2 + 1][1] = t4[3];
        }
    };
    auto mmas = [&](uint32_t (*fa)[4], uint32_t (*fb)[2]) {
        #pragma unroll
        for (int mt = 0; mt < 2; mt++)
            #pragma unroll
            for (int nt = 0; nt < 4; nt++)
                mma16816(acc[mt][nt], fa[mt], fb[nt]);
    };

    // prologue: 3 stages in flight, fragments for (kt=0, kc=0)
    load_tile(0, 0);
    load_tile(1, 1);
    load_tile(2, 2);
    asm volatile("cp.async.wait_group 2;" ::: "memory");   // stage 0 complete
    __syncthreads();
    ldsA(curA, sbase, 0);
    ldsB(curB, sbase, 0);

    for (int kt = 0; kt < KT; kt++) {
        // committed = 3 + kt; wait 1 -> stages <= kt+1 complete
        asm volatile("cp.async.wait_group 1;" ::: "memory");
        __syncthreads();                        // visible; stage (kt+3)%4 free
        if (kt + 3 < KT) load_tile(kt + 3, (kt + 3) & 3);

        const uint32_t sbC = sbase + (kt & 3) * STG_B;
        const uint32_t sbN = sbase + ((kt + 1) & 3) * STG_B;

        // kc = 0: prefetch kc=1 fragments, then issue MMAs on cur
        ldsA(nxtA, sbC, 1);
        ldsB(nxtB, sbC, 1);
        mmas(curA, curB);

        // kc = 1: prefetch next ktile's kc=0 fragments (stage kt+1 complete),
        // then issue MMAs on nxt. Final iteration reads a stale stage; unused.
        ldsA(curA, sbN, 0);
        ldsB(curB, sbN, 0);
        mmas(nxtA, nxtB);
    }

    // ---------------- epilogue ----------------
    #pragma unroll
    for (int mt = 0; mt < 2; mt++) {
        int r0 = bm + wm + mt * 16 + (lane >> 2);
        int r1 = r0 + 8;
        int   ja0 = 0, ja1 = 0, ja2 = 0, jb0 = 0, jb1 = 0, jb2 = 0;
        float wa0 = 0, wa1 = 0, wa2 = 0, wb0 = 0, wb1 = 0, wb2 = 0;
        if (MODE == 1) {
            ja0 = g_idx[r0 * 3 + 0]; ja1 = g_idx[r0 * 3 + 1]; ja2 = g_idx[r0 * 3 + 2];
            wa0 = g_w[r0 * 3 + 0];   wa1 = g_w[r0 * 3 + 1];   wa2 = g_w[r0 * 3 + 2];
            jb0 = g_idx[r1 * 3 + 0]; jb1 = g_idx[r1 * 3 + 1]; jb2 = g_idx[r1 * 3 + 2];
            wb0 = g_w[r1 * 3 + 0];   wb1 = g_w[r1 * 3 + 1];   wb2 = g_w[r1 * 3 + 2];
        }
        #pragma unroll
        for (int nt = 0; nt < 4; nt++) {
            int cg = bn + wn + nt * 8 + (lane & 3) * 2;
            float v0 = acc[mt][nt][0], v1 = acc[mt][nt][1];
            float v2 = acc[mt][nt][2], v3 = acc[mt][nt][3];
            if (MODE != 0) {
                float2 bv = *(const float2*)(bias + cg);
                v0 += bv.x; v1 += bv.y; v2 += bv.x; v3 += bv.y;
            }
            if (MODE == 1) {
                __half2 z;
                z = *(const __half2*)(Zt + (size_t)ja0 * 512 + cg);
                v0 += wa0 * __low2float(z); v1 += wa0 * __high2float(z);
                z = *(const __half2*)(Zt + (size_t)ja1 * 512 + cg);
                v0 += wa1 * __low2float(z); v1 += wa1 * __high2float(z);
                z = *(const __half2*)(Zt + (size_t)ja2 * 512 + cg);
                v0 += wa2 * __low2float(z); v1 += wa2 * __high2float(z);
                z = *(const __half2*)(Zt + (size_t)jb0 * 512 + cg);
                v2 += wb0 * __low2float(z); v3 += wb0 * __high2float(z);
                z = *(const __half2*)(Zt + (size_t)jb1 * 512 + cg);
                v2 += wb1 * __low2float(z); v3 += wb1 * __high2float(z);
                z = *(const __half2*)(Zt + (size_t)jb2 * 512 + cg);
                v2 += wb2 * __low2float(z); v3 += wb2 * __high2float(z);
            }
            if (MODE != 0) {
                v0 = fmaxf(v0, 0.0f); v1 = fmaxf(v1, 0.0f);
                v2 = fmaxf(v2, 0.0f); v3 = fmaxf(v3, 0.0f);
            }
            if (MODE == 2) {
                *(float2*)(outF + (size_t)r0 * ldout + cg) = make_float2(v0, v1);
                *(float2*)(outF + (size_t)r1 * ldout + cg) = make_float2(v2, v3);
            } else {
                *(__half2*)(outH + (size_t)r0 * ldout + cg) =
                    __halves2half2(__float2half_rn(v0), __float2half_rn(v1));
                *(__half2*)(outH + (size_t)r1 * ldout + cg) =
                    __halves2half2(__float2half_rn(v2), __float2half_rn(v3));
            }
        }
    }
}

// ---------------------------------------------------------------- launch
extern "C" void kernel_launch(void* const* d_in, const int* in_sizes, int n_in,
                              void* d_out, int out_size) {
    const float* x          = (const float*)d_in[0];
    const float* pos        = (const float*)d_in[1];
    const float* x_skip     = (const float*)d_in[3];
    const float* pos_skip   = (const float*)d_in[4];
    const int*   batch_skip = (const int*)d_in[5];
    const float* W1         = (const float*)d_in[6];
    const float* b1         = (const float*)d_in[7];
    const float* W2         = (const float*)d_in[8];
    const float* b2         = (const float*)d_in[9];
    float* out = (float*)d_out;

    __half *Xh, *Sh, *H1h, *Z, *W1aT, *W1bT, *W2T;
    cudaGetSymbolAddress((void**)&Xh, g_Xh);
    cudaGetSymbolAddress((void**)&Sh, g_Sh);
    cudaGetSymbolAddress((void**)&H1h, g_H1h);
    cudaGetSymbolAddress((void**)&Z, g_Z);
    cudaGetSymbolAddress((void**)&W1aT, g_W1aT);
    cudaGetSymbolAddress((void**)&W1bT, g_W1bT);
    cudaGetSymbolAddress((void**)&W2T, g_W2T);

    cudaFuncSetAttribute(gemm_mma<0>, cudaFuncAttributeMaxDynamicSharedMemorySize, GEMM_SMEM);
    cudaFuncSetAttribute(gemm_mma<1>, cudaFuncAttributeMaxDynamicSharedMemorySize, GEMM_SMEM);
    cudaFuncSetAttribute(gemm_mma<2>, cudaFuncAttributeMaxDynamicSharedMemorySize, GEMM_SMEM);

    // 1) merged prep (knn + converts + transposes + tail)
    const long long FULL = (long long)MM * CC + (long long)MM * 3 + MM;
    int prep_blocks = ((long long)out_size >= FULL) ? PB_END : PB_TAIL;
    prep_kernel<<<prep_blocks, 256>>>(pos, pos_skip, x, x_skip, W1, W2,
                                      batch_skip, out);

    // 2) Z = x @ W1a   [16384 x 512] fp16, K=256
    gemm_mma<0><<<dim3(8, MC / 128), 256, GEMM_SMEM>>>(
        Xh, W1aT, nullptr, nullptr, nullptr, Z, 256, 512);

    // 3) H1 = relu(x_skip @ W1b + gather(Z) + b1)  [65536 x 512], K=256
    gemm_mma<1><<<dim3(8, MM / 128), 256, GEMM_SMEM>>>(
        Sh, W1bT, b1, Z, nullptr, H1h, 256, 512);

    // 4) out = relu(H1 @ W2 + b2)  [65536 x 256], K=512
    gemm_mma<2><<<dim3(4, MM / 128), 256, GEMM_SMEM>>>(
        H1h, W2T, b2, nullptr, out, nullptr, 512, 256);
}

// round 16
// speedup vs baseline: 1.0826x; 1.0826x over previous
#include <cuda_runtime.h>
#include <cuda_fp16.h>
#include <math.h>
#include <stdint.h>

// ---------------------------------------------------------------- constants
#define BB   16
#define NC   1024
#define NF   4096
#define CC   256
#define MM   (BB * NF)      // 65536 fine points
#define MC   (BB * NC)      // 16384 coarse points

// ---------------------------------------------------------------- scratch
__device__ __align__(16) __half g_Xh[MC * 256];        // x  (fp16)
__device__ __align__(16) __half g_Sh[MM * 256];        // x_skip (fp16)
__device__ __align__(16) __half g_H1h[MM * 512];       // layer1 out (fp16)
__device__ __align__(16) __half g_Z[MC * 512];         // x @ W1a (fp16)
__device__ __align__(16) __half g_W1aT[512 * 256];     // [N=512][K=256]
__device__ __align__(16) __half g_W1bT[512 * 256];
__device__ __align__(16) __half g_W2T[256 * 512];      // [N=256][K=512]
__device__ int   g_idx[MM * 3];
__device__ float g_w[MM * 3];

// ---------------------------------------------------------------- helpers
__device__ __forceinline__ uint32_t smem_u32(const void* p) {
    uint32_t a;
    asm("{ .reg .u64 t; cvta.to.shared.u64 t, %1; cvt.u32.u64 %0, t; }"
        : "=r"(a) : "l"(p));
    return a;
}
__device__ __forceinline__ void cp16(uint32_t dst, const void* src) {
    asm volatile("cp.async.cg.shared.global [%0], [%1], 16;" :: "r"(dst), "l"(src));
}
__device__ __forceinline__ void ldsm4(uint32_t* r, uint32_t addr) {
    asm volatile("ldmatrix.sync.aligned.m8n8.x4.shared.b16 {%0,%1,%2,%3}, [%4];"
        : "=r"(r[0]), "=r"(r[1]), "=r"(r[2]), "=r"(r[3]) : "r"(addr));
}
__device__ __forceinline__ void mma16816(float* d, const uint32_t* a, const uint32_t* b) {
    asm volatile("mma.sync.aligned.m16n8k16.row.col.f32.f16.f16.f32 "
        "{%0,%1,%2,%3}, {%4,%5,%6,%7}, {%8,%9}, {%0,%1,%2,%3};"
        : "+f"(d[0]), "+f"(d[1]), "+f"(d[2]), "+f"(d[3])
        : "r"(a[0]), "r"(a[1]), "r"(a[2]), "r"(a[3]), "r"(b[0]), "r"(b[1]));
}

// ---------------------------------------------------------------- merged prep
// converts now do 4 float4 per thread -> 4x fewer blocks
#define PB_KNN   0
#define PB_X     256
#define PB_S     (PB_X + 1024)
#define PB_T1    (PB_S + 4096)
#define PB_T2    (PB_T1 + 128)
#define PB_T3    (PB_T2 + 128)
#define PB_TAIL  (PB_T3 + 128)       // 5760
#define PB_END   (PB_TAIL + 768)     // 6528

__global__ __launch_bounds__(256)
void prep_kernel(const float* __restrict__ pos_c, const float* __restrict__ pos_f,
                 const float* __restrict__ x, const float* __restrict__ x_skip,
                 const float* __restrict__ W1, const float* __restrict__ W2,
                 const int* __restrict__ batch_skip,
                 float* __restrict__ out) {
    __shared__ float4 sh4[NC];            // 16 KB; aliased by transpose
    const int bid = blockIdx.x, tid = threadIdx.x;

    if (bid < PB_X) {
        // ---------------- KNN ----------------
        int i = bid * 256 + tid;
        int b = i >> 12;
        const float* pc = pos_c + (size_t)b * NC * 3;
        for (int t = tid; t < NC; t += 256)
            sh4[t] = make_float4(pc[t * 3 + 0], pc[t * 3 + 1], pc[t * 3 + 2], 0.0f);
        __syncthreads();

        float px = pos_f[i * 3 + 0], py = pos_f[i * 3 + 1], pz = pos_f[i * 3 + 2];
        float d0 = INFINITY, d1 = INFINITY, d2 = INFINITY;
        int   i0 = 0, i1 = 0, i2 = 0;
        #pragma unroll 8
        for (int j = 0; j < NC; j++) {
            float4 p = sh4[j];
            float dx = px - p.x, dy = py - p.y, dz = pz - p.z;
            float d = dx * dx + dy * dy + dz * dz;
            if (d < d2) {
                if (d < d1) {
                    if (d < d0) { d2 = d1; i2 = i1; d1 = d0; i1 = i0; d0 = d; i0 = j; }
                    else        { d2 = d1; i2 = i1; d1 = d;  i1 = j; }
                } else          { d2 = d;  i2 = j; }
            }
        }
        float w0 = 1.0f / (d0 + 1e-16f), w1 = 1.0f / (d1 + 1e-16f), w2 = 1.0f / (d2 + 1e-16f);
        float inv = 1.0f / (w0 + w1 + w2);
        int base = b * NC;
        g_idx[i * 3 + 0] = base + i0;  g_idx[i * 3 + 1] = base + i1;  g_idx[i * 3 + 2] = base + i2;
        g_w[i * 3 + 0] = w0 * inv;     g_w[i * 3 + 1] = w1 * inv;     g_w[i * 3 + 2] = w2 * inv;
    } else if (bid < PB_T1) {
        // ---------------- fp32 -> fp16 converts (4 float4 per thread) ----------------
        const float* src;  __half* dst;  int t0;
        if (bid < PB_S) { t0 = (bid - PB_X) * 1024 + tid;  src = x;      dst = g_Xh; }
        else            { t0 = (bid - PB_S) * 1024 + tid;  src = x_skip; dst = g_Sh; }
        #pragma unroll
        for (int l = 0; l < 4; l++) {
            int t = t0 + l * 256;
            float4 v = ((const float4*)src)[t];
            __half h[4];
            h[0] = __float2half_rn(v.x);  h[1] = __float2half_rn(v.y);
            h[2] = __float2half_rn(v.z);  h[3] = __float2half_rn(v.w);
            ((uint2*)dst)[t] = *(uint2*)h;
        }
    } else if (bid < PB_TAIL) {
        // ---------------- weight transposes ----------------
        float* tt = (float*)sh4;              // 32x33 tile
        const float* in;  __half* oh;  int N, Kt, b2;
        if (bid < PB_T2)      { b2 = bid - PB_T1; in = W1;             oh = g_W1aT; N = 512; Kt = 256; }
        else if (bid < PB_T3) { b2 = bid - PB_T2; in = W1 + 256 * 512; oh = g_W1bT; N = 512; Kt = 256; }
        else                  { b2 = bid - PB_T3; in = W2;             oh = g_W2T;  N = 256; Kt = 512; }
        int nbx = N / 32;
        int n0 = (b2 % nbx) * 32, k0 = (b2 / nbx) * 32;
        int xx = tid & 31, yy = tid >> 5;
        for (int j = yy; j < 32; j += 8)
            tt[j * 33 + xx] = in[(size_t)(k0 + j) * N + n0 + xx];
        __syncthreads();
        for (int j = yy; j < 32; j += 8)
            oh[(size_t)(n0 + j) * Kt + k0 + xx] = __float2half_rn(tt[xx * 33 + j]);
    } else {
        // ---------------- tail outputs ----------------
        int t = (bid - PB_TAIL) * 256 + tid;
        const size_t POS_OFF = (size_t)MM * CC;
        const size_t BAT_OFF = POS_OFF + (size_t)MM * 3;
        out[POS_OFF + t] = ((const float*)pos_f)[t];   // pos_f == pos_skip
        if (t < MM) out[BAT_OFF + t] = (float)batch_skip[t];
    }
}

// ---------------------------------------------------------------- mma.sync GEMM
// CTA 128x128, warp 64x32 (8 warps: 2M x 4N), BK=64 (4 kc-phases per ktile),
// 3-stage cp.async with rolling lookahead (wait_group 1: stage kt ready, kt+1
// in flight). All phases of a ktile read ONE stage -> no cross-stage fragment
// hazard. One sync per 64-K. 2 CTAs/SM.  [r14-verified config]
// MODE 0: C -> fp16 (Z)   MODE 1: relu(C+b+gather(Z)) -> fp16 (H1)
// MODE 2: relu(C+b) -> fp32 (out)
#define ROW_B     144                 // 64 fp16 = 128B data + 16B pad
#define TILE_B    (128 * ROW_B)       // 18432
#define STG_B     (2 * TILE_B)        // 36864 (A + B)
#define NSTG      3
#define GEMM_SMEM (NSTG * STG_B)      // 110592

template<int MODE>
__global__ __launch_bounds__(256, 2)
void gemm_mma(const __half* __restrict__ A, const __half* __restrict__ B,
              const float* __restrict__ bias, const __half* __restrict__ Zt,
              float* __restrict__ outF, __half* __restrict__ outH,
              int K, int ldout) {
    extern __shared__ __align__(128) char smem[];
    const uint32_t sbase = smem_u32(smem);
    const int tid  = threadIdx.x;
    const int wid  = tid >> 5, lane = tid & 31;
    const int wm   = (wid >> 2) * 64;          // 0/64
    const int wn   = (wid & 3) * 32;           // 0..96
    const int bm   = blockIdx.y * 128, bn = blockIdx.x * 128;
    const int KT   = K >> 6;                   // BK=64 tiles
    const int rA = tid >> 3, qA = tid & 7;     // 8 chunks of 16B per 128B row

    auto load_tile = [&](int kt, int stg) {
        const uint32_t sb = sbase + stg * STG_B;
        const size_t ka = (size_t)kt * 64;
        #pragma unroll
        for (int l = 0; l < 4; l++) {
            int r = rA + l * 32;
            cp16(sb + r * ROW_B + qA * 16, A + (size_t)(bm + r) * K + ka + qA * 8);
            cp16(sb + TILE_B + r * ROW_B + qA * 16, B + (size_t)(bn + r) * K + ka + qA * 8);
        }
        asm volatile("cp.async.commit_group;" ::: "memory");
    };

    float acc[4][4][4];
    #pragma unroll
    for (int a = 0; a < 4; a++)
        #pragma unroll
        for (int b = 0; b < 4; b++)
            #pragma unroll
            for (int c = 0; c < 4; c++) acc[a][b][c] = 0.0f;

    const int lmr = (lane & 7) + ((lane >> 3) & 1) * 8;
    const int lmc = (lane >> 4) & 1;
    const uint32_t aBase = (wm + lmr) * ROW_B + lmc * 16;
    const uint32_t bBase = TILE_B + (wn + lmr) * ROW_B + lmc * 16;

    uint32_t curA[4][4], curB[4][2], nxtA[4][4], nxtB[4][2];

    auto ldsA = [&](uint32_t (*fr)[4], uint32_t sb, int kc) {
        #pragma unroll
        for (int mt = 0; mt < 4; mt++)
            ldsm4(fr[mt], sb + aBase + mt * 16 * ROW_B + kc * 32);
    };
    auto ldsB = [&](uint32_t (*fr)[2], uint32_t sb, int kc) {
        #pragma unroll
        for (int bt = 0; bt < 2; bt++) {
            uint32_t t4[4];
            ldsm4(t4, sb + bBase + bt * 16 * ROW_B + kc * 32);
            fr[bt * 2][0] = t4[0];     fr[bt * 2][1] = t4[2];
            fr[bt * 2 + 1][0] = t4[1]; fr[bt * 2 + 1][1] = t4[3];
        }
    };
    auto mmas = [&](uint32_t (*fa)[4], uint32_t (*fb)[2]) {
        #pragma unroll
        for (int mt = 0; mt < 4; mt++)
            #pragma unroll
            for (int nt = 0; nt < 4; nt++)
                mma16816(acc[mt][nt], fa[mt], fb[nt]);
    };

    // prologue: 2 of 3 stages in flight
    load_tile(0, 0);
    load_tile(1, 1);

    for (int kt = 0; kt < KT; kt++) {
        // committed = 2 + kt; wait 1 -> groups 0..kt complete -> stage kt ready
        asm volatile("cp.async.wait_group 1;" ::: "memory");
        __syncthreads();   // data visible; stage (kt+2)%3 free (read in iter kt-1)
        if (kt + 2 < KT) load_tile(kt + 2, (kt + 2) % NSTG);

        const uint32_t sb = sbase + (kt % NSTG) * STG_B;

        // 4 kc-phases within this stage, fragment double-buffered
        ldsA(curA, sb, 0); ldsB(curB, sb, 0);   // exposed once per 64-K
        ldsA(nxtA, sb, 1); ldsB(nxtB, sb, 1);
        mmas(curA, curB);
        ldsA(curA, sb, 2); ldsB(curB, sb, 2);
        mmas(nxtA, nxtB);
        ldsA(nxtA, sb, 3); ldsB(nxtB, sb, 3);
        mmas(curA, curB);
        mmas(nxtA, nxtB);
    }

    // ---------------- epilogue ----------------
    #pragma unroll
    for (int mt = 0; mt < 4; mt++) {
        int r0 = bm + wm + mt * 16 + (lane >> 2);
        int r1 = r0 + 8;
        int   ja0 = 0, ja1 = 0, ja2 = 0, jb0 = 0, jb1 = 0, jb2 = 0;
        float wa0 = 0, wa1 = 0, wa2 = 0, wb0 = 0, wb1 = 0, wb2 = 0;
        if (MODE == 1) {
            ja0 = g_idx[r0 * 3 + 0]; ja1 = g_idx[r0 * 3 + 1]; ja2 = g_idx[r0 * 3 + 2];
            wa0 = g_w[r0 * 3 + 0];   wa1 = g_w[r0 * 3 + 1];   wa2 = g_w[r0 * 3 + 2];
            jb0 = g_idx[r1 * 3 + 0]; jb1 = g_idx[r1 * 3 + 1]; jb2 = g_idx[r1 * 3 + 2];
            wb0 = g_w[r1 * 3 + 0];   wb1 = g_w[r1 * 3 + 1];   wb2 = g_w[r1 * 3 + 2];
        }
        #pragma unroll
        for (int nt = 0; nt < 4; nt++) {
            int cg = bn + wn + nt * 8 + (lane & 3) * 2;
            float v0 = acc[mt][nt][0], v1 = acc[mt][nt][1];
            float v2 = acc[mt][nt][2], v3 = acc[mt][nt][3];
            if (MODE != 0) {
                float2 bv = *(const float2*)(bias + cg);
                v0 += bv.x; v1 += bv.y; v2 += bv.x; v3 += bv.y;
            }
            if (MODE == 1) {
                __half2 z;
                z = *(const __half2*)(Zt + (size_t)ja0 * 512 + cg);
                v0 += wa0 * __low2float(z); v1 += wa0 * __high2float(z);
                z = *(const __half2*)(Zt + (size_t)ja1 * 512 + cg);
                v0 += wa1 * __low2float(z); v1 += wa1 * __high2float(z);
                z = *(const __half2*)(Zt + (size_t)ja2 * 512 + cg);
                v0 += wa2 * __low2float(z); v1 += wa2 * __high2float(z);
                z = *(const __half2*)(Zt + (size_t)jb0 * 512 + cg);
                v2 += wb0 * __low2float(z); v3 += wb0 * __high2float(z);
                z = *(const __half2*)(Zt + (size_t)jb1 * 512 + cg);
                v2 += wb1 * __low2float(z); v3 += wb1 * __high2float(z);
                z = *(const __half2*)(Zt + (size_t)jb2 * 512 + cg);
                v2 += wb2 * __low2float(z); v3 += wb2 * __high2float(z);
            }
            if (MODE != 0) {
                v0 = fmaxf(v0, 0.0f); v1 = fmaxf(v1, 0.0f);
                v2 = fmaxf(v2, 0.0f); v3 = fmaxf(v3, 0.0f);
            }
            if (MODE == 2) {
                *(float2*)(outF + (size_t)r0 * ldout + cg) = make_float2(v0, v1);
                *(float2*)(outF + (size_t)r1 * ldout + cg) = make_float2(v2, v3);
            } else {
                *(__half2*)(outH + (size_t)r0 * ldout + cg) =
                    __halves2half2(__float2half_rn(v0), __float2half_rn(v1));
                *(__half2*)(outH + (size_t)r1 * ldout + cg) =
                    __halves2half2(__float2half_rn(v2), __float2half_rn(v3));
            }
        }
    }
}

// ---------------------------------------------------------------- launch
extern "C" void kernel_launch(void* const* d_in, const int* in_sizes, int n_in,
                              void* d_out, int out_size) {
    const float* x          = (const float*)d_in[0];
    const float* pos        = (const float*)d_in[1];
    const float* x_skip     = (const float*)d_in[3];
    const float* pos_skip   = (const float*)d_in[4];
    const int*   batch_skip = (const int*)d_in[5];
    const float* W1         = (const float*)d_in[6];
    const float* b1         = (const float*)d_in[7];
    const float* W2         = (const float*)d_in[8];
    const float* b2         = (const float*)d_in[9];
    float* out = (float*)d_out;

    __half *Xh, *Sh, *H1h, *Z, *W1aT, *W1bT, *W2T;
    cudaGetSymbolAddress((void**)&Xh, g_Xh);
    cudaGetSymbolAddress((void**)&Sh, g_Sh);
    cudaGetSymbolAddress((void**)&H1h, g_H1h);
    cudaGetSymbolAddress((void**)&Z, g_Z);
    cudaGetSymbolAddress((void**)&W1aT, g_W1aT);
    cudaGetSymbolAddress((void**)&W1bT, g_W1bT);
    cudaGetSymbolAddress((void**)&W2T, g_W2T);

    cudaFuncSetAttribute(gemm_mma<0>, cudaFuncAttributeMaxDynamicSharedMemorySize, GEMM_SMEM);
    cudaFuncSetAttribute(gemm_mma<1>, cudaFuncAttributeMaxDynamicSharedMemorySize, GEMM_SMEM);
    cudaFuncSetAttribute(gemm_mma<2>, cudaFuncAttributeMaxDynamicSharedMemorySize, GEMM_SMEM);

    // 1) merged prep (knn + converts + transposes + tail)
    const long long FULL = (long long)MM * CC + (long long)MM * 3 + MM;
    int prep_blocks = ((long long)out_size >= FULL) ? PB_END : PB_TAIL;
    prep_kernel<<<prep_blocks, 256>>>(pos, pos_skip, x, x_skip, W1, W2,
                                      batch_skip, out);

    // 2) Z = x @ W1a   [16384 x 512] fp16, K=256
    gemm_mma<0><<<dim3(4, MC / 128), 256, GEMM_SMEM>>>(
        Xh, W1aT, nullptr, nullptr, nullptr, Z, 256, 512);

    // 3) H1 = relu(x_skip @ W1b + gather(Z) + b1)  [65536 x 512], K=256
    gemm_mma<1><<<dim3(4, MM / 128), 256, GEMM_SMEM>>>(
        Sh, W1bT, b1, Z, nullptr, H1h, 256, 512);

    // 4) out = relu(H1 @ W2 + b2)  [65536 x 256], K=512
    gemm_mma<2><<<dim3(2, MM / 128), 256, GEMM_SMEM>>>(
        H1h, W2T, b2, nullptr, out, nullptr, 512, 256);
}

// round 17
// speedup vs baseline: 1.1010x; 1.0170x over previous
#include <cuda_runtime.h>
#include <cuda_fp16.h>
#include <math.h>
#include <stdint.h>

// ---------------------------------------------------------------- constants
#define BB   16
#define NC   1024
#define NF   4096
#define CC   256
#define MM   (BB * NF)      // 65536 fine points
#define MC   (BB * NC)      // 16384 coarse points

// ---------------------------------------------------------------- scratch
__device__ __align__(16) __half g_Xh[MC * 256];        // x  (fp16)
__device__ __align__(16) __half g_Sh[MM * 256];        // x_skip (fp16)
__device__ __align__(16) __half g_H1h[MM * 512];       // layer1 out (fp16)
__device__ __align__(16) __half g_Z[MC * 512];         // x @ W1a (fp16)
__device__ __align__(16) __half g_W1aT[512 * 256];     // [N=512][K=256]
__device__ __align__(16) __half g_W1bT[512 * 256];
__device__ __align__(16) __half g_W2T[256 * 512];      // [N=256][K=512]
__device__ int   g_idx[MM * 3];
__device__ float g_w[MM * 3];

// ---------------------------------------------------------------- helpers
__device__ __forceinline__ uint32_t smem_u32(const void* p) {
    uint32_t a;
    asm("{ .reg .u64 t; cvta.to.shared.u64 t, %1; cvt.u32.u64 %0, t; }"
        : "=r"(a) : "l"(p));
    return a;
}
__device__ __forceinline__ void cp16(uint32_t dst, const void* src) {
    asm volatile("cp.async.cg.shared.global [%0], [%1], 16;" :: "r"(dst), "l"(src));
}
__device__ __forceinline__ void ldsm4(uint32_t* r, uint32_t addr) {
    asm volatile("ldmatrix.sync.aligned.m8n8.x4.shared.b16 {%0,%1,%2,%3}, [%4];"
        : "=r"(r[0]), "=r"(r[1]), "=r"(r[2]), "=r"(r[3]) : "r"(addr));
}
__device__ __forceinline__ void mma16816(float* d, const uint32_t* a, const uint32_t* b) {
    asm volatile("mma.sync.aligned.m16n8k16.row.col.f32.f16.f16.f32 "
        "{%0,%1,%2,%3}, {%4,%5,%6,%7}, {%8,%9}, {%0,%1,%2,%3};"
        : "+f"(d[0]), "+f"(d[1]), "+f"(d[2]), "+f"(d[3])
        : "r"(a[0]), "r"(a[1]), "r"(a[2]), "r"(a[3]), "r"(b[0]), "r"(b[1]));
}

// ---------------------------------------------------------------- merged prep
#define PB_KNN   0
#define PB_X     256
#define PB_S     (PB_X + 4096)
#define PB_T1    (PB_S + 16384)
#define PB_T2    (PB_T1 + 128)
#define PB_T3    (PB_T2 + 128)
#define PB_TAIL  (PB_T3 + 128)       // 21120
#define PB_END   (PB_TAIL + 768)     // 21888

__global__ __launch_bounds__(256)
void prep_kernel(const float* __restrict__ pos_c, const float* __restrict__ pos_f,
                 const float* __restrict__ x, const float* __restrict__ x_skip,
                 const float* __restrict__ W1, const float* __restrict__ W2,
                 const int* __restrict__ batch_skip,
                 float* __restrict__ out) {
    __shared__ float4 sh4[NC];            // 16 KB; aliased by transpose
    const int bid = blockIdx.x, tid = threadIdx.x;

    if (bid < PB_X) {
        // ---------------- KNN ----------------
        int i = bid * 256 + tid;
        int b = i >> 12;
        const float* pc = pos_c + (size_t)b * NC * 3;
        for (int t = tid; t < NC; t += 256)
            sh4[t] = make_float4(pc[t * 3 + 0], pc[t * 3 + 1], pc[t * 3 + 2], 0.0f);
        __syncthreads();

        float px = pos_f[i * 3 + 0], py = pos_f[i * 3 + 1], pz = pos_f[i * 3 + 2];
        float d0 = INFINITY, d1 = INFINITY, d2 = INFINITY;
        int   i0 = 0, i1 = 0, i2 = 0;
        #pragma unroll 4
        for (int j = 0; j < NC; j++) {
            float4 p = sh4[j];
            float dx = px - p.x, dy = py - p.y, dz = pz - p.z;
            float d = dx * dx + dy * dy + dz * dz;
            if (d < d2) {
                if (d < d1) {
                    if (d < d0) { d2 = d1; i2 = i1; d1 = d0; i1 = i0; d0 = d; i0 = j; }
                    else        { d2 = d1; i2 = i1; d1 = d;  i1 = j; }
                } else          { d2 = d;  i2 = j; }
            }
        }
        float w0 = 1.0f / (d0 + 1e-16f), w1 = 1.0f / (d1 + 1e-16f), w2 = 1.0f / (d2 + 1e-16f);
        float inv = 1.0f / (w0 + w1 + w2);
        int base = b * NC;
        g_idx[i * 3 + 0] = base + i0;  g_idx[i * 3 + 1] = base + i1;  g_idx[i * 3 + 2] = base + i2;
        g_w[i * 3 + 0] = w0 * inv;     g_w[i * 3 + 1] = w1 * inv;     g_w[i * 3 + 2] = w2 * inv;
    } else if (bid < PB_T1) {
        // ---------------- fp32 -> fp16 converts ----------------
        const float* src;  __half* dst;  int t;
        if (bid < PB_S) { t = (bid - PB_X) * 256 + tid;  src = x;      dst = g_Xh; }
        else            { t = (bid - PB_S) * 256 + tid;  src = x_skip; dst = g_Sh; }
        float4 v = ((const float4*)src)[t];
        __half h[4];
        h[0] = __float2half_rn(v.x);  h[1] = __float2half_rn(v.y);
        h[2] = __float2half_rn(v.z);  h[3] = __float2half_rn(v.w);
        ((uint2*)dst)[t] = *(uint2*)h;
    } else if (bid < PB_TAIL) {
        // ---------------- weight transposes ----------------
        float* tt = (float*)sh4;              // 32x33 tile
        const float* in;  __half* oh;  int N, Kt, b2;
        if (bid < PB_T2)      { b2 = bid - PB_T1; in = W1;             oh = g_W1aT; N = 512; Kt = 256; }
        else if (bid < PB_T3) { b2 = bid - PB_T2; in = W1 + 256 * 512; oh = g_W1bT; N = 512; Kt = 256; }
        else                  { b2 = bid - PB_T3; in = W2;             oh = g_W2T;  N = 256; Kt = 512; }
        int nbx = N / 32;
        int n0 = (b2 % nbx) * 32, k0 = (b2 / nbx) * 32;
        int xx = tid & 31, yy = tid >> 5;
        for (int j = yy; j < 32; j += 8)
            tt[j * 33 + xx] = in[(size_t)(k0 + j) * N + n0 + xx];
        __syncthreads();
        for (int j = yy; j < 32; j += 8)
            oh[(size_t)(n0 + j) * Kt + k0 + xx] = __float2half_rn(tt[xx * 33 + j]);
    } else {
        // ---------------- tail outputs ----------------
        int t = (bid - PB_TAIL) * 256 + tid;
        const size_t POS_OFF = (size_t)MM * CC;
        const size_t BAT_OFF = POS_OFF + (size_t)MM * 3;
        out[POS_OFF + t] = ((const float*)pos_f)[t];   // pos_f == pos_skip
        if (t < MM) out[BAT_OFF + t] = (float)batch_skip[t];
    }
}

// ---------------------------------------------------------------- mma.sync GEMM
// CTA 128x128, warp 64x32 (8 warps: 2M x 4N), BK=64 (4 kc-phases per ktile),
// 3-stage cp.async with rolling lookahead (wait_group 1: stage kt ready, kt+1
// in flight). All phases of a ktile read ONE stage -> no cross-stage fragment
// hazard. One sync per 64-K. 2 CTAs/SM.  [r14-verified best config]
// MODE 0: C -> fp16 (Z)   MODE 1: relu(C+b+gather(Z)) -> fp16 (H1)
// MODE 2: relu(C+b) -> fp32 (out)
#define ROW_B     144                 // 64 fp16 = 128B data + 16B pad
#define TILE_B    (128 * ROW_B)       // 18432
#define STG_B     (2 * TILE_B)        // 36864 (A + B)
#define NSTG      3
#define GEMM_SMEM (NSTG * STG_B)      // 110592

template<int MODE>
__global__ __launch_bounds__(256, 2)
void gemm_mma(const __half* __restrict__ A, const __half* __restrict__ B,
              const float* __restrict__ bias, const __half* __restrict__ Zt,
              float* __restrict__ outF, __half* __restrict__ outH,
              int K, int ldout) {
    extern __shared__ __align__(128) char smem[];
    const uint32_t sbase = smem_u32(smem);
    const int tid  = threadIdx.x;
    const int wid  = tid >> 5, lane = tid & 31;
    const int wm   = (wid >> 2) * 64;          // 0/64
    const int wn   = (wid & 3) * 32;           // 0..96
    const int bm   = blockIdx.y * 128, bn = blockIdx.x * 128;
    const int KT   = K >> 6;                   // BK=64 tiles
    const int rA = tid >> 3, qA = tid & 7;     // 8 chunks of 16B per 128B row

    auto load_tile = [&](int kt, int stg) {
        const uint32_t sb = sbase + stg * STG_B;
        const size_t ka = (size_t)kt * 64;
        #pragma unroll
        for (int l = 0; l < 4; l++) {
            int r = rA + l * 32;
            cp16(sb + r * ROW_B + qA * 16, A + (size_t)(bm + r) * K + ka + qA * 8);
            cp16(sb + TILE_B + r * ROW_B + qA * 16, B + (size_t)(bn + r) * K + ka + qA * 8);
        }
        asm volatile("cp.async.commit_group;" ::: "memory");
    };

    float acc[4][4][4];
    #pragma unroll
    for (int a = 0; a < 4; a++)
        #pragma unroll
        for (int b = 0; b < 4; b++)
            #pragma unroll
            for (int c = 0; c < 4; c++) acc[a][b][c] = 0.0f;

    const int lmr = (lane & 7) + ((lane >> 3) & 1) * 8;
    const int lmc = (lane >> 4) & 1;
    const uint32_t aBase = (wm + lmr) * ROW_B + lmc * 16;
    const uint32_t bBase = TILE_B + (wn + lmr) * ROW_B + lmc * 16;

    uint32_t curA[4][4], curB[4][2], nxtA[4][4], nxtB[4][2];

    auto ldsA = [&](uint32_t (*fr)[4], uint32_t sb, int kc) {
        #pragma unroll
        for (int mt = 0; mt < 4; mt++)
            ldsm4(fr[mt], sb + aBase + mt * 16 * ROW_B + kc * 32);
    };
    auto ldsB = [&](uint32_t (*fr)[2], uint32_t sb, int kc) {
        #pragma unroll
        for (int bt = 0; bt < 2; bt++) {
            uint32_t t4[4];
            ldsm4(t4, sb + bBase + bt * 16 * ROW_B + kc * 32);
            fr[bt * 2][0] = t4[0];     fr[bt * 2][1] = t4[2];
            fr[bt * 2 + 1][0] = t4[1]; fr[bt * 2 + 1][1] = t4[3];
        }
    };
    auto mmas = [&](uint32_t (*fa)[4], uint32_t (*fb)[2]) {
        #pragma unroll
        for (int mt = 0; mt < 4; mt++)
            #pragma unroll
            for (int nt = 0; nt < 4; nt++)
                mma16816(acc[mt][nt], fa[mt], fb[nt]);
    };

    // prologue: 2 of 3 stages in flight
    load_tile(0, 0);
    load_tile(1, 1);

    for (int kt = 0; kt < KT; kt++) {
        // committed = 2 + kt; wait 1 -> groups 0..kt complete -> stage kt ready
        asm volatile("cp.async.wait_group 1;" ::: "memory");
        __syncthreads();   // data visible; stage (kt+2)%3 free (read in iter kt-1)
        if (kt + 2 < KT) load_tile(kt + 2, (kt + 2) % NSTG);

        const uint32_t sb = sbase + (kt % NSTG) * STG_B;

        // 4 kc-phases within this stage, fragment double-buffered
        ldsA(curA, sb, 0); ldsB(curB, sb, 0);   // exposed once per 64-K
        ldsA(nxtA, sb, 1); ldsB(nxtB, sb, 1);
        mmas(curA, curB);
        ldsA(curA, sb, 2); ldsB(curB, sb, 2);
        mmas(nxtA, nxtB);
        ldsA(nxtA, sb, 3); ldsB(nxtB, sb, 3);
        mmas(curA, curB);
        mmas(nxtA, nxtB);
    }

    // ---------------- epilogue ----------------
    #pragma unroll
    for (int mt = 0; mt < 4; mt++) {
        int r0 = bm + wm + mt * 16 + (lane >> 2);
        int r1 = r0 + 8;
        int   ja0 = 0, ja1 = 0, ja2 = 0, jb0 = 0, jb1 = 0, jb2 = 0;
        float wa0 = 0, wa1 = 0, wa2 = 0, wb0 = 0, wb1 = 0, wb2 = 0;
        if (MODE == 1) {
            ja0 = g_idx[r0 * 3 + 0]; ja1 = g_idx[r0 * 3 + 1]; ja2 = g_idx[r0 * 3 + 2];
            wa0 = g_w[r0 * 3 + 0];   wa1 = g_w[r0 * 3 + 1];   wa2 = g_w[r0 * 3 + 2];
            jb0 = g_idx[r1 * 3 + 0]; jb1 = g_idx[r1 * 3 + 1]; jb2 = g_idx[r1 * 3 + 2];
            wb0 = g_w[r1 * 3 + 0];   wb1 = g_w[r1 * 3 + 1];   wb2 = g_w[r1 * 3 + 2];
        }
        #pragma unroll
        for (int nt = 0; nt < 4; nt++) {
            int cg = bn + wn + nt * 8 + (lane & 3) * 2;
            float v0 = acc[mt][nt][0], v1 = acc[mt][nt][1];
            float v2 = acc[mt][nt][2], v3 = acc[mt][nt][3];
            if (MODE != 0) {
                float2 bv = *(const float2*)(bias + cg);
                v0 += bv.x; v1 += bv.y; v2 += bv.x; v3 += bv.y;
            }
            if (MODE == 1) {
                __half2 z;
                z = *(const __half2*)(Zt + (size_t)ja0 * 512 + cg);
                v0 += wa0 * __low2float(z); v1 += wa0 * __high2float(z);
                z = *(const __half2*)(Zt + (size_t)ja1 * 512 + cg);
                v0 += wa1 * __low2float(z); v1 += wa1 * __high2float(z);
                z = *(const __half2*)(Zt + (size_t)ja2 * 512 + cg);
                v0 += wa2 * __low2float(z); v1 += wa2 * __high2float(z);
                z = *(const __half2*)(Zt + (size_t)jb0 * 512 + cg);
                v2 += wb0 * __low2float(z); v3 += wb0 * __high2float(z);
                z = *(const __half2*)(Zt + (size_t)jb1 * 512 + cg);
                v2 += wb1 * __low2float(z); v3 += wb1 * __high2float(z);
                z = *(const __half2*)(Zt + (size_t)jb2 * 512 + cg);
                v2 += wb2 * __low2float(z); v3 += wb2 * __high2float(z);
            }
            if (MODE != 0) {
                v0 = fmaxf(v0, 0.0f); v1 = fmaxf(v1, 0.0f);
                v2 = fmaxf(v2, 0.0f); v3 = fmaxf(v3, 0.0f);
            }
            if (MODE == 2) {
                *(float2*)(outF + (size_t)r0 * ldout + cg) = make_float2(v0, v1);
                *(float2*)(outF + (size_t)r1 * ldout + cg) = make_float2(v2, v3);
            } else {
                *(__half2*)(outH + (size_t)r0 * ldout + cg) =
                    __halves2half2(__float2half_rn(v0), __float2half_rn(v1));
                *(__half2*)(outH + (size_t)r1 * ldout + cg) =
                    __halves2half2(__float2half_rn(v2), __float2half_rn(v3));
            }
        }
    }
}

// ---------------------------------------------------------------- launch
extern "C" void kernel_launch(void* const* d_in, const int* in_sizes, int n_in,
                              void* d_out, int out_size) {
    const float* x          = (const float*)d_in[0];
    const float* pos        = (const float*)d_in[1];
    const float* x_skip     = (const float*)d_in[3];
    const float* pos_skip   = (const float*)d_in[4];
    const int*   batch_skip = (const int*)d_in[5];
    const float* W1         = (const float*)d_in[6];
    const float* b1         = (const float*)d_in[7];
    const float* W2         = (const float*)d_in[8];
    const float* b2         = (const float*)d_in[9];
    float* out = (float*)d_out;

    __half *Xh, *Sh, *H1h, *Z, *W1aT, *W1bT, *W2T;
    cudaGetSymbolAddress((void**)&Xh, g_Xh);
    cudaGetSymbolAddress((void**)&Sh, g_Sh);
    cudaGetSymbolAddress((void**)&H1h, g_H1h);
    cudaGetSymbolAddress((void**)&Z, g_Z);
    cudaGetSymbolAddress((void**)&W1aT, g_W1aT);
    cudaGetSymbolAddress((void**)&W1bT, g_W1bT);
    cudaGetSymbolAddress((void**)&W2T, g_W2T);

    cudaFuncSetAttribute(gemm_mma<0>, cudaFuncAttributeMaxDynamicSharedMemorySize, GEMM_SMEM);
    cudaFuncSetAttribute(gemm_mma<1>, cudaFuncAttributeMaxDynamicSharedMemorySize, GEMM_SMEM);
    cudaFuncSetAttribute(gemm_mma<2>, cudaFuncAttributeMaxDynamicSharedMemorySize, GEMM_SMEM);

    // 1) merged prep (knn + converts + transposes + tail)
    const long long FULL = (long long)MM * CC + (long long)MM * 3 + MM;
    int prep_blocks = ((long long)out_size >= FULL) ? PB_END : PB_TAIL;
    prep_kernel<<<prep_blocks, 256>>>(pos, pos_skip, x, x_skip, W1, W2,
                                      batch_skip, out);

    // 2) Z = x @ W1a   [16384 x 512] fp16, K=256
    gemm_mma<0><<<dim3(4, MC / 128), 256, GEMM_SMEM>>>(
        Xh, W1aT, nullptr, nullptr, nullptr, Z, 256, 512);

    // 3) H1 = relu(x_skip @ W1b + gather(Z) + b1)  [65536 x 512], K=256
    gemm_mma<1><<<dim3(4, MM / 128), 256, GEMM_SMEM>>>(
        Sh, W1bT, b1, Z, nullptr, H1h, 256, 512);

    // 4) out = relu(H1 @ W2 + b2)  [65536 x 256], K=512
    gemm_mma<2><<<dim3(2, MM / 128), 256, GEMM_SMEM>>>(
        H1h, W2T, b2, nullptr, out, nullptr, 512, 256);
}